// round 4
// baseline (speedup 1.0000x reference)
#include <cuda_runtime.h>
#include <cuda_bf16.h>

#define NB      256      // batch
#define SEQ     65
#define HID     512
#define HEADS   8
#define NP      64       // patches
#define PDIM    256
#define ROWS    (NB*SEQ) // 16640
#define OUTD    10

// ---------------- scratch (__device__ globals; no runtime alloc) ~280 MB ----------------
__device__ float g_Z [NB*SEQ*HID];   // 34 MB
__device__ float g_Zn[NB*SEQ*HID];   // 34 MB
__device__ float g_R [NB*SEQ*HID];   // 34 MB
__device__ float g_E [NB*NP*HID];    // 33.5 MB
__device__ float g_Qh[ROWS*HID];     // 34 MB (one head at a time)
__device__ float g_Kh[ROWS*HID];     // 34 MB
__device__ float g_Vh[ROWS*HID];     // 34 MB
__device__ float g_Oh[ROWS*HID];     // 34 MB

// ---------------- fp32 tiled GEMM: 128x128x16, 256 thr, 8x8 microtile ----------------
// C = A @ B (+bias) (+res) (+= if accum)   A:[M,K] lda (K-contig), B:[K,N] ldb (N-contig)
// Requires M%128==0, N%128==0, K%16==0 (true at all call sites)
__global__ __launch_bounds__(256, 2)
void gemm128(const float* __restrict__ A, const float* __restrict__ B,
             float* __restrict__ C, int K, int lda, int ldb, int ldc,
             const float* __restrict__ bias,
             const float* __restrict__ res, int ldres, int accum)
{
    __shared__ float As[16][132];   // padded: STS bank spread
    __shared__ float Bs[16][128];

    const int tid = threadIdx.x;
    const int tx = tid & 15, ty = tid >> 4;
    const int m0 = blockIdx.x * 128, n0 = blockIdx.y * 128;

    float acc[8][8];
#pragma unroll
    for (int i = 0; i < 8; i++)
#pragma unroll
        for (int j = 0; j < 8; j++) acc[i][j] = 0.f;

    for (int k0 = 0; k0 < K; k0 += 16) {
        // A tile: 128 rows x 16 k = 512 float4; 2 per thread
#pragma unroll
        for (int l = 0; l < 2; l++) {
            int idx = tid + l * 256;
            int row = idx >> 2, kc = (idx & 3) * 4;
            float4 f = *(const float4*)&A[(long)(m0 + row) * lda + k0 + kc];
            As[kc + 0][row] = f.x;
            As[kc + 1][row] = f.y;
            As[kc + 2][row] = f.z;
            As[kc + 3][row] = f.w;
        }
        // B tile: 16 k x 128 n = 512 float4; 2 per thread
#pragma unroll
        for (int l = 0; l < 2; l++) {
            int idx = tid + l * 256;
            int kr = idx >> 5, nc = (idx & 31) * 4;
            *(float4*)&Bs[kr][nc] = *(const float4*)&B[(long)(k0 + kr) * ldb + n0 + nc];
        }
        __syncthreads();
#pragma unroll
        for (int k = 0; k < 16; k++) {
            float4 a0 = *(const float4*)&As[k][ty * 8];
            float4 a1 = *(const float4*)&As[k][ty * 8 + 4];
            float4 b0 = *(const float4*)&Bs[k][tx * 8];
            float4 b1 = *(const float4*)&Bs[k][tx * 8 + 4];
            float a[8] = {a0.x, a0.y, a0.z, a0.w, a1.x, a1.y, a1.z, a1.w};
            float b[8] = {b0.x, b0.y, b0.z, b0.w, b1.x, b1.y, b1.z, b1.w};
#pragma unroll
            for (int i = 0; i < 8; i++)
#pragma unroll
                for (int j = 0; j < 8; j++) acc[i][j] += a[i] * b[j];
        }
        __syncthreads();
    }

#pragma unroll
    for (int i = 0; i < 8; i++) {
        int m = m0 + ty * 8 + i;
        long rowC = (long)m * ldc + n0 + tx * 8;
#pragma unroll
        for (int h = 0; h < 2; h++) {
            float4 c = {acc[i][h*4+0], acc[i][h*4+1], acc[i][h*4+2], acc[i][h*4+3]};
            int nb = n0 + tx * 8 + h * 4;
            if (bias) {
                c.x += bias[nb+0]; c.y += bias[nb+1]; c.z += bias[nb+2]; c.w += bias[nb+3];
            }
            if (res) {
                float4 r = *(const float4*)&res[(long)m * ldres + nb];
                c.x += r.x; c.y += r.y; c.z += r.z; c.w += r.w;
            }
            if (accum) {
                float4 r = *(const float4*)&C[rowC + h * 4];
                c.x += r.x; c.y += r.y; c.z += r.z; c.w += r.w;
            }
            *(float4*)&C[rowC + h * 4] = c;
        }
    }
}

// ---------------- assemble Z = concat(cls, E) + pos ----------------
__global__ void assemble_kernel(const float* __restrict__ cls, const float* __restrict__ pos)
{
    long idx = (long)blockIdx.x * 256 + threadIdx.x;
    if (idx >= (long)NB * SEQ * HID) return;
    int e = (int)(idx % HID);
    long r = idx / HID;
    int s = (int)(r % SEQ);
    long n = r / SEQ;
    float v = pos[s * HID + e];
    if (s == 0) v += cls[e];
    else        v += g_E[(n * NP + (s - 1)) * (long)HID + e];
    g_Z[idx] = v;
}

// ---------------- LayerNorm over whole (SEQ,HID) slab per sample ----------------
__global__ __launch_bounds__(1024)
void ln_kernel(const float* __restrict__ in, float* __restrict__ out,
               const float* __restrict__ w, const float* __restrict__ b)
{
    const int n = blockIdx.x;
    const float* x = in + (long)n * SEQ * HID;
    float* y = out + (long)n * SEQ * HID;
    float s = 0.f, ss = 0.f;
    for (int i = threadIdx.x; i < SEQ * HID; i += 1024) {
        float v = x[i]; s += v; ss += v * v;
    }
    __shared__ float red[64];
#pragma unroll
    for (int o = 16; o; o >>= 1) {
        s  += __shfl_down_sync(0xffffffffu, s, o);
        ss += __shfl_down_sync(0xffffffffu, ss, o);
    }
    int wid = threadIdx.x >> 5, lane = threadIdx.x & 31;
    if (lane == 0) { red[wid] = s; red[32 + wid] = ss; }
    __syncthreads();
    if (threadIdx.x == 0) {
        float S = 0.f, SS = 0.f;
        for (int i = 0; i < 32; i++) { S += red[i]; SS += red[32 + i]; }
        float inv = 1.0f / (SEQ * HID);
        float mu = S * inv;
        float var = SS * inv - mu * mu;
        red[0] = mu; red[1] = rsqrtf(var + 1e-5f);
    }
    __syncthreads();
    float mu = red[0], rinv = red[1];
    for (int i = threadIdx.x; i < SEQ * HID; i += 1024)
        y[i] = (x[i] - mu) * rinv * w[i] + b[i];
}

// ---------------- fused attention per sample (single head buffers) ----------------
// scores = q @ k^T * scale -> softmax -> O = attn @ v
// Scores accumulate in SMEM (no per-thread register arrays => cheap compile).
__global__ __launch_bounds__(256)
void attn_kernel()
{
    const int n = blockIdx.x;
    const float* q = g_Qh + (long)n * SEQ * HID;
    const float* k = g_Kh + (long)n * SEQ * HID;
    const float* v = g_Vh + (long)n * SEQ * HID;
    float* out = g_Oh + (long)n * SEQ * HID;

    __shared__ float sc[SEQ * SEQ];    // 16.9 KB
    __shared__ float work[SEQ][66];    // 17.2 KB (q in cols [0,32), k in [33,65))

    const int tid = threadIdx.x;

    for (int idx = tid; idx < SEQ * SEQ; idx += 256) sc[idx] = 0.f;
    __syncthreads();

    // scores += q_chunk @ k_chunk^T, 32-wide k-chunks
    for (int k0 = 0; k0 < HID; k0 += 32) {
        for (int i = tid; i < SEQ * 32; i += 256) {
            int s = i >> 5, j = i & 31;
            work[s][j]      = q[s * HID + k0 + j];
            work[s][33 + j] = k[s * HID + k0 + j];
        }
        __syncthreads();
        for (int idx = tid; idx < SEQ * SEQ; idx += 256) {
            int s = idx / SEQ;
            int t = idx - s * SEQ;
            float a = 0.f;
#pragma unroll
            for (int j = 0; j < 32; j++)
                a += work[s][j] * work[t][33 + j];
            sc[idx] += a;
        }
        __syncthreads();
    }

    // softmax rows (scale = 1/512^2 per reference)
    if (tid < SEQ) {
        const float scale = 1.0f / (512.0f * 512.0f);
        float m = -1e30f;
        for (int t = 0; t < SEQ; t++) m = fmaxf(m, sc[tid * SEQ + t] * scale);
        float sum = 0.f;
        for (int t = 0; t < SEQ; t++) {
            float e = __expf(sc[tid * SEQ + t] * scale - m);
            sc[tid * SEQ + t] = e; sum += e;
        }
        float r = 1.0f / sum;
        for (int t = 0; t < SEQ; t++) sc[tid * SEQ + t] *= r;
    }
    __syncthreads();

    // O = attn @ v, 64-wide e-chunks
    for (int e0 = 0; e0 < HID; e0 += 64) {
        for (int i = tid; i < SEQ * 64; i += 256) {
            int t = i >> 6, j = i & 63;
            work[t][j] = v[t * HID + e0 + j];
        }
        __syncthreads();
        for (int idx = tid; idx < SEQ * 64; idx += 256) {
            int s = idx >> 6, e = idx & 63;
            float a = 0.f;
            for (int t = 0; t < SEQ; t++)
                a += sc[s * SEQ + t] * work[t][e];
            out[(long)s * HID + e0 + e] = a;
        }
        __syncthreads();
    }
}

// ---------------- classification head ----------------
__global__ void head_kernel(const float* __restrict__ Wh, const float* __restrict__ bh,
                            float* __restrict__ out)
{
    const int n = blockIdx.x;
    const int o = threadIdx.y;       // 10
    const int lane = threadIdx.x;    // 32
    const float* z = g_Z + (long)n * SEQ * HID;  // row s=0
    float a = 0.f;
    for (int e = lane; e < HID; e += 32) a += z[e] * Wh[e * OUTD + o];
#pragma unroll
    for (int off = 16; off; off >>= 1) a += __shfl_down_sync(0xffffffffu, a, off);
    if (lane == 0) out[n * OUTD + o] = tanhf(a + bh[o]);
}

// ---------------- host launcher ----------------
static float* sym_addr(const void* symbol)
{
    void* p = nullptr;
    cudaGetSymbolAddress(&p, symbol);
    return (float*)p;
}

extern "C" void kernel_launch(void* const* d_in, const int* in_sizes, int n_in,
                              void* d_out, int out_size)
{
    const float* X    = (const float*)d_in[0];
    const float* Wp   = (const float*)d_in[1];
    const float* bp   = (const float*)d_in[2];
    const float* cls  = (const float*)d_in[3];
    const float* pos  = (const float*)d_in[4];
    const float* ln1w = (const float*)d_in[5];
    const float* ln1b = (const float*)d_in[6];
    const float* Wq   = (const float*)d_in[7];
    const float* bq   = (const float*)d_in[8];
    const float* Wk   = (const float*)d_in[9];
    const float* bk   = (const float*)d_in[10];
    const float* Wv   = (const float*)d_in[11];
    const float* bv   = (const float*)d_in[12];
    const float* Wo   = (const float*)d_in[13];
    const float* bo   = (const float*)d_in[14];
    const float* ln2w = (const float*)d_in[15];
    const float* ln2b = (const float*)d_in[16];
    const float* W2   = (const float*)d_in[17];
    const float* b2   = (const float*)d_in[18];
    const float* Wh   = (const float*)d_in[19];
    const float* bh   = (const float*)d_in[20];
    float* out = (float*)d_out;

    float* Z  = sym_addr(g_Z);
    float* Zn = sym_addr(g_Zn);
    float* R  = sym_addr(g_R);
    float* E  = sym_addr(g_E);
    float* Qh = sym_addr(g_Qh);
    float* Kh = sym_addr(g_Kh);
    float* Vh = sym_addr(g_Vh);
    float* Oh = sym_addr(g_Oh);

    const long WSTRIDE = (long)HID * HID;  // per-head weight stride

    // 1) patch embed: E = X(as [16384,256]) @ Wp + bp
    {
        dim3 grid((NB * NP) / 128, HID / 128);
        gemm128<<<grid, 256>>>(X, Wp, E, PDIM, PDIM, HID, HID,
                               bp, nullptr, 0, 0);
    }
    // 2) Z = concat(cls, E) + pos
    {
        long total = (long)NB * SEQ * HID;
        assemble_kernel<<<(unsigned)((total + 255) / 256), 256>>>(cls, pos);
    }

    dim3 gRow(ROWS / 128, HID / 128);

    for (int blk = 0; blk < 6; blk++) {
        // LN1: Z -> Zn
        ln_kernel<<<NB, 1024>>>(Z, Zn, ln1w, ln1b);

        // per-head streamed attention + Wo accumulation into R
        for (int h = 0; h < HEADS; h++) {
            gemm128<<<gRow, 256>>>(Zn, Wq + (long)h * WSTRIDE, Qh, HID, HID, HID, HID,
                                   bq + (long)h * HID, nullptr, 0, 0);
            gemm128<<<gRow, 256>>>(Zn, Wk + (long)h * WSTRIDE, Kh, HID, HID, HID, HID,
                                   bk + (long)h * HID, nullptr, 0, 0);
            gemm128<<<gRow, 256>>>(Zn, Wv + (long)h * WSTRIDE, Vh, HID, HID, HID, HID,
                                   bv + (long)h * HID, nullptr, 0, 0);

            attn_kernel<<<NB, 256>>>();

            // h==0: R = Oh@Wo_h + bo + Z ; h>0: R += Oh@Wo_h
            if (h == 0)
                gemm128<<<gRow, 256>>>(Oh, Wo + (long)h * WSTRIDE, R, HID, HID, HID, HID,
                                       bo, Z, HID, 0);
            else
                gemm128<<<gRow, 256>>>(Oh, Wo + (long)h * WSTRIDE, R, HID, HID, HID, HID,
                                       nullptr, nullptr, 0, 1);
        }

        // LN2: R -> Zn
        ln_kernel<<<NB, 1024>>>(R, Zn, ln2w, ln2b);

        // Z = Zn @ W2 + b2
        gemm128<<<gRow, 256>>>(Zn, W2, Z, HID, HID, HID, HID,
                               b2, nullptr, 0, 0);
    }

    // head: out = tanh(Z[:,0] @ Wh + bh)
    head_kernel<<<NB, dim3(32, 10)>>>(Wh, bh, out);
    (void)in_sizes; (void)n_in; (void)out_size;
}